// round 8
// baseline (speedup 1.0000x reference)
#include <cuda_runtime.h>
#include <cuda_fp16.h>
#include <mma.h>
#include <cstdint>
#include <cstring>

using namespace nvcuda;

#define NPOINTS   262144
#define NNET      512
#define IN_F      256
#define OUT_F     256
#define BM        64
#define BN        128
#define BK        32
#define N_CHUNKS  (IN_F / BK)        /* 8 */
#define SUBTILES  12                 /* ceil(768/64) */
#define NCOLS     (OUT_F / BN)       /* 2 */
#define THREADS   128

// fp16 tile strides (halves), padded so LDSM phases spread banks
#define LDAH  40    /* 32 + 8 */
#define LDBH  136   /* 128 + 8 */
#define LDE   132   /* fp32 epilogue/bias stride */

// ---- dynamic SMEM layout (bytes) ----
#define AH_BYTES    (BM * LDAH * 2)              /* 5120  */
#define BH_BYTES    (BK * LDBH * 2)              /* 8704  */
#define TILE_STRIDE (AH_BYTES + BH_BYTES)        /* 13824, x2 buffers */
#define BIAS_OFF    (2 * TILE_STRIDE)            /* 27648 */
#define BIAS_BYTES  (16 * LDE * 4)               /* 8448  */
#define SMEM_TOTAL  (BIAS_OFF + BIAS_BYTES)      /* 36096; partial-epi (32*LDE*4=16896) overlays tiles */

__device__ int g_seg[NNET];   // start point index per network

// ---------------- helpers ----------------
__device__ __forceinline__ uint32_t h2u(__half2 h) {
    uint32_t u; memcpy(&u, &h, 4); return u;
}
__device__ __forceinline__ uint2 pack_f4(float4 v) {
    uint2 r;
    r.x = h2u(__float22half2_rn(make_float2(v.x, v.y)));
    r.y = h2u(__float22half2_rn(make_float2(v.z, v.w)));
    return r;
}

// ---------------- kernel 1: segment starts ----------------
__global__ void seg_kernel(const int* __restrict__ net_id) {
    int p = blockIdx.x * blockDim.x + threadIdx.x;
    if (p >= NPOINTS) return;
    int nid = net_id[p];
    if (p == 0 || net_id[p - 1] != nid) g_seg[nid] = p;
}

// -------- kernel 2: grouped GEMM (fp16 HMMA, 64x128 CTA tile, 4 CTAs/SM) --------
__global__ void __launch_bounds__(THREADS, 4)
grouped_gemm_kernel(const float* __restrict__ x, const float* __restrict__ weight,
                    const float* __restrict__ bias, float* __restrict__ out) {
    int bx   = blockIdx.x;
    int ncol = bx & (NCOLS - 1);
    int sub  = (bx >> 1) % SUBTILES;
    int n    = bx / (SUBTILES * NCOLS);

    int s0 = g_seg[n];
    int s1 = (n == NNET - 1) ? NPOINTS : g_seg[n + 1];
    int row0 = s0 + sub * BM;
    int cnt = s1 - row0;
    if (cnt <= 0) return;                 // empty sub-tile: whole CTA exits
    if (cnt > BM) cnt = BM;
    int ncol0 = ncol * BN;

    extern __shared__ char smem[];
    float* smf = reinterpret_cast<float*>(smem);

    int tid = threadIdx.x;
    int wid = tid >> 5;
    int warp_m = wid >> 1;                // 0..1 -> 32-row slab
    int warp_n = wid & 1;                 // 0..1 -> 64-col slab

    const float* wsrc = weight + (size_t)n * IN_F * OUT_F;   // [in][out]: row-major KxN

    // per-thread load coordinates (fixed across chunks)
    int ar[4], ac[4]; bool av[4];         // A: 64 rows x 8 float4 = 512 -> 4/thread
    int br[8], bc[8];                     // B: 32 rows x 32 float4 = 1024 -> 8/thread
#pragma unroll
    for (int j = 0; j < 4; j++) {
        int idx = tid + j * THREADS;
        ar[j] = idx >> 3; ac[j] = idx & 7;
        av[j] = ar[j] < cnt;
    }
#pragma unroll
    for (int j = 0; j < 8; j++) {
        int idx = tid + j * THREADS;
        br[j] = idx >> 5; bc[j] = idx & 31;
    }

    // ---- bias replicated tile (16 rows x 128 cols fp32) ----
    {
        int rowb = tid >> 3, colb = (tid & 7) * 16;
        const float* bsrc = bias + (size_t)n * OUT_F + ncol0 + colb;
        float* dst = smf + (BIAS_OFF / 4) + rowb * LDE + colb;
#pragma unroll
        for (int q = 0; q < 4; q++)
            *reinterpret_cast<float4*>(dst + q * 4) =
                *reinterpret_cast<const float4*>(bsrc + q * 4);
    }

    // ---- prefetch chunk 0 into fp16 registers ----
    uint2 pa[4], pb[8];
    {
        const float* xs = x + (size_t)row0 * IN_F;
        const float* ws = wsrc + ncol0;
#pragma unroll
        for (int j = 0; j < 4; j++) {
            float4 v = make_float4(0.f, 0.f, 0.f, 0.f);
            if (av[j]) v = *reinterpret_cast<const float4*>(xs + (size_t)ar[j] * IN_F + ac[j] * 4);
            pa[j] = pack_f4(v);
        }
#pragma unroll
        for (int j = 0; j < 8; j++) {
            float4 v = *reinterpret_cast<const float4*>(ws + (size_t)br[j] * OUT_F + bc[j] * 4);
            pb[j] = pack_f4(v);
        }
    }

    __syncthreads();   // bias tile ready

    // ---- accumulators preloaded with bias (warp tile 32x64 -> acc[2][4]) ----
    wmma::fragment<wmma::accumulator, 16, 16, 16, float> acc[2][4];
#pragma unroll
    for (int nt = 0; nt < 4; nt++) {
        wmma::load_matrix_sync(acc[0][nt],
                               smf + (BIAS_OFF / 4) + warp_n * 64 + nt * 16,
                               LDE, wmma::mem_row_major);
        acc[1][nt] = acc[0][nt];
    }

    // ---- mainloop: one __syncthreads per chunk, double-buffered fp16 tiles ----
    for (int c = 0; c < N_CHUNKS; c++) {
        int buf = c & 1;
        char* tbase = smem + buf * TILE_STRIDE;
#pragma unroll
        for (int j = 0; j < 4; j++)
            *reinterpret_cast<uint2*>(tbase + (ar[j] * LDAH + ac[j] * 4) * 2) = pa[j];
#pragma unroll
        for (int j = 0; j < 8; j++)
            *reinterpret_cast<uint2*>(tbase + AH_BYTES + (br[j] * LDBH + bc[j] * 4) * 2) = pb[j];
        __syncthreads();   // tiles[buf] ready; also orders mma(c-1) before next STS of buf^1

        // prefetch chunk c+1 (LDG issued here, hidden under mma below)
        if (c + 1 < N_CHUNKS) {
            int k0 = (c + 1) * BK;
            const float* xs = x + (size_t)row0 * IN_F + k0;
            const float* ws = wsrc + (size_t)k0 * OUT_F + ncol0;
#pragma unroll
            for (int j = 0; j < 4; j++) {
                float4 v = make_float4(0.f, 0.f, 0.f, 0.f);
                if (av[j]) v = *reinterpret_cast<const float4*>(xs + (size_t)ar[j] * IN_F + ac[j] * 4);
                pa[j] = pack_f4(v);
            }
#pragma unroll
            for (int j = 0; j < 8; j++) {
                float4 v = *reinterpret_cast<const float4*>(ws + (size_t)br[j] * OUT_F + bc[j] * 4);
                pb[j] = pack_f4(v);
            }
        }

        const __half* Ah = reinterpret_cast<const __half*>(smem + buf * TILE_STRIDE);
        const __half* Bh = reinterpret_cast<const __half*>(smem + buf * TILE_STRIDE + AH_BYTES);
#pragma unroll
        for (int ks = 0; ks < 2; ks++) {
            int k0 = ks * 16;
            wmma::fragment<wmma::matrix_b, 16, 16, 16, __half, wmma::row_major> bf[4];
#pragma unroll
            for (int nt = 0; nt < 4; nt++)
                wmma::load_matrix_sync(bf[nt], Bh + k0 * LDBH + warp_n * 64 + nt * 16, LDBH);
#pragma unroll
            for (int mt = 0; mt < 2; mt++) {
                wmma::fragment<wmma::matrix_a, 16, 16, 16, __half, wmma::row_major> af;
                wmma::load_matrix_sync(af, Ah + (warp_m * 32 + mt * 16) * LDAH + k0, LDAH);
#pragma unroll
                for (int nt = 0; nt < 4; nt++)
                    wmma::mma_sync(acc[mt][nt], af, bf[nt], acc[mt][nt]);
            }
        }
    }

    // ---- epilogue (bias already in acc) ----
    if (cnt == BM) {
        // full tile: store fragments straight to gmem, no SMEM round-trip
#pragma unroll
        for (int mt = 0; mt < 2; mt++)
#pragma unroll
            for (int nt = 0; nt < 4; nt++)
                wmma::store_matrix_sync(
                    out + (size_t)(row0 + warp_m * 32 + mt * 16) * OUT_F
                        + ncol0 + warp_n * 64 + nt * 16,
                    acc[mt][nt], OUT_F, wmma::mem_row_major);
    } else {
        // partial tile: two 32-row half-passes through SMEM with row masking
        __syncthreads();   // all mma done before overwriting tiles region
        int c4 = tid & 31, rb = tid >> 5;
#pragma unroll
        for (int half = 0; half < 2; half++) {
            if (warp_m == half) {
#pragma unroll
                for (int mt = 0; mt < 2; mt++)
#pragma unroll
                    for (int nt = 0; nt < 4; nt++)
                        wmma::store_matrix_sync(
                            smf + (mt * 16) * LDE + warp_n * 64 + nt * 16,
                            acc[mt][nt], LDE, wmma::mem_row_major);
            }
            __syncthreads();
#pragma unroll
            for (int i = 0; i < 8; i++) {
                int rl = rb + i * 4;
                int r = half * 32 + rl;
                if (r < cnt)
                    *reinterpret_cast<float4*>(out + (size_t)(row0 + r) * OUT_F + ncol0 + c4 * 4) =
                        *reinterpret_cast<const float4*>(smf + rl * LDE + c4 * 4);
            }
            __syncthreads();
        }
    }
}

// ---------------- launcher ----------------
extern "C" void kernel_launch(void* const* d_in, const int* in_sizes, int n_in,
                              void* d_out, int out_size) {
    const float* x      = (const float*)d_in[0];
    const float* weight = (const float*)d_in[1];
    const float* bias   = (const float*)d_in[2];
    const int*   net_id = (const int*)d_in[3];
    // d_in[4] = slot_id (unused: points are sorted, slots contiguous within segments)
    float* out = (float*)d_out;

    cudaFuncSetAttribute(grouped_gemm_kernel,
                         cudaFuncAttributeMaxDynamicSharedMemorySize, SMEM_TOTAL);

    seg_kernel<<<NPOINTS / 256, 256>>>(net_id);
    grouped_gemm_kernel<<<NNET * SUBTILES * NCOLS, THREADS, SMEM_TOTAL>>>(x, weight, bias, out);
}

// round 9
// speedup vs baseline: 1.0401x; 1.0401x over previous
#include <cuda_runtime.h>
#include <cuda_fp16.h>
#include <mma.h>
#include <cstdint>
#include <cstring>

using namespace nvcuda;

#define NPOINTS   262144
#define NNET      512
#define IN_F      256
#define OUT_F     256
#define BM        128
#define BN        128
#define BK        64
#define N_CHUNKS  (IN_F / BK)        /* 4 */
#define SUBTILES  6                  /* ceil(768/128) */
#define NCOLS     (OUT_F / BN)       /* 2 */
#define THREADS   256

// fp16 tile strides (halves), padded so LDSM phases spread banks
#define LDAH  72    /* 64 + 8 */
#define LDBH  136   /* 128 + 8 */
#define LDE   132   /* fp32 epilogue/bias stride */

// ---- dynamic SMEM layout (bytes) ----
#define AH_BYTES    (BM * LDAH * 2)              /* 18432 */
#define BH_BYTES    (BK * LDBH * 2)              /* 17408 */
#define TILE_STRIDE (AH_BYTES + BH_BYTES)        /* 35840, x2 buffers */
#define BIAS_OFF    (2 * TILE_STRIDE)            /* 71680 */
#define BIAS_BYTES  (16 * LDE * 4)               /* 8448  */
#define SMEM_TOTAL  (BIAS_OFF + BIAS_BYTES)      /* 80128; partial-epi (64*LDE*4=33792) overlays tiles */

__device__ int g_seg[NNET];   // start point index per network

// ---------------- helpers ----------------
__device__ __forceinline__ uint32_t h2u(__half2 h) {
    uint32_t u; memcpy(&u, &h, 4); return u;
}
__device__ __forceinline__ uint2 pack_f4(float4 v) {
    uint2 r;
    r.x = h2u(__float22half2_rn(make_float2(v.x, v.y)));
    r.y = h2u(__float22half2_rn(make_float2(v.z, v.w)));
    return r;
}

// ---------------- kernel 1: segment starts ----------------
__global__ void seg_kernel(const int* __restrict__ net_id) {
    int p = blockIdx.x * blockDim.x + threadIdx.x;
    if (p >= NPOINTS) return;
    int nid = net_id[p];
    if (p == 0 || net_id[p - 1] != nid) g_seg[nid] = p;
}

// -------- kernel 2: grouped GEMM (fp16 HMMA, BK=64, 4 syncs total, 2 CTAs/SM) --------
__global__ void __launch_bounds__(THREADS, 2)
grouped_gemm_kernel(const float* __restrict__ x, const float* __restrict__ weight,
                    const float* __restrict__ bias, float* __restrict__ out) {
    int bx   = blockIdx.x;
    int ncol = bx & (NCOLS - 1);
    int sub  = (bx >> 1) % SUBTILES;
    int n    = bx / (SUBTILES * NCOLS);

    int s0 = g_seg[n];
    int s1 = (n == NNET - 1) ? NPOINTS : g_seg[n + 1];
    int row0 = s0 + sub * BM;
    int cnt = s1 - row0;
    if (cnt <= 0) return;                 // empty sub-tile: whole CTA exits
    if (cnt > BM) cnt = BM;
    int ncol0 = ncol * BN;

    extern __shared__ char smem[];
    float* smf = reinterpret_cast<float*>(smem);

    int tid = threadIdx.x;
    int wid = tid >> 5;
    int warp_m = wid >> 2;                // 0..1 -> 64-row slab
    int warp_n = wid & 3;                 // 0..3 -> 32-col slab

    const float* wsrc = weight + (size_t)n * IN_F * OUT_F;   // [in][out]: row-major KxN

    // per-thread load coordinates (fixed across chunks)
    int ar[8], ac[8]; bool av[8];         // A: 128 rows x 16 float4 = 2048 -> 8/thread
    int br[8], bc[8];                     // B: 64 rows  x 32 float4 = 2048 -> 8/thread
#pragma unroll
    for (int j = 0; j < 8; j++) {
        int idx = tid + j * THREADS;
        ar[j] = idx >> 4; ac[j] = idx & 15;
        av[j] = ar[j] < cnt;
        br[j] = idx >> 5; bc[j] = idx & 31;
    }

    // ---- bias replicated tile (16 rows x 128 cols fp32) ----
    {
        int rowb = tid >> 4, colb = (tid & 15) * 8;
        const float* bsrc = bias + (size_t)n * OUT_F + ncol0 + colb;
        float* dst = smf + (BIAS_OFF / 4) + rowb * LDE + colb;
        *reinterpret_cast<float4*>(dst)     = *reinterpret_cast<const float4*>(bsrc);
        *reinterpret_cast<float4*>(dst + 4) = *reinterpret_cast<const float4*>(bsrc + 4);
    }

    // ---- prefetch chunk 0 into fp16 registers ----
    uint2 pa[8], pb[8];
    {
        const float* xs = x + (size_t)row0 * IN_F;
        const float* ws = wsrc + ncol0;
#pragma unroll
        for (int j = 0; j < 8; j++) {
            float4 v = make_float4(0.f, 0.f, 0.f, 0.f);
            if (av[j]) v = *reinterpret_cast<const float4*>(xs + (size_t)ar[j] * IN_F + ac[j] * 4);
            pa[j] = pack_f4(v);
        }
#pragma unroll
        for (int j = 0; j < 8; j++) {
            float4 v = *reinterpret_cast<const float4*>(ws + (size_t)br[j] * OUT_F + bc[j] * 4);
            pb[j] = pack_f4(v);
        }
    }

    __syncthreads();   // bias tile ready

    // ---- accumulators preloaded with bias ----
    wmma::fragment<wmma::accumulator, 16, 16, 16, float> acc[4][2];
#pragma unroll
    for (int nt = 0; nt < 2; nt++) {
        wmma::load_matrix_sync(acc[0][nt],
                               smf + (BIAS_OFF / 4) + warp_n * 32 + nt * 16,
                               LDE, wmma::mem_row_major);
#pragma unroll
        for (int mt = 1; mt < 4; mt++) acc[mt][nt] = acc[0][nt];
    }

    // ---- mainloop: one __syncthreads per K=64 chunk, double-buffered fp16 tiles ----
    for (int c = 0; c < N_CHUNKS; c++) {
        int buf = c & 1;
        char* tbase = smem + buf * TILE_STRIDE;
#pragma unroll
        for (int j = 0; j < 8; j++)
            *reinterpret_cast<uint2*>(tbase + (ar[j] * LDAH + ac[j] * 4) * 2) = pa[j];
#pragma unroll
        for (int j = 0; j < 8; j++)
            *reinterpret_cast<uint2*>(tbase + AH_BYTES + (br[j] * LDBH + bc[j] * 4) * 2) = pb[j];
        __syncthreads();   // tiles[buf] ready; also orders mma(c-1) before next STS of buf^1

        // prefetch chunk c+1 (LDG issued here, hidden under 32 HMMAs below)
        if (c + 1 < N_CHUNKS) {
            int k0 = (c + 1) * BK;
            const float* xs = x + (size_t)row0 * IN_F + k0;
            const float* ws = wsrc + (size_t)k0 * OUT_F + ncol0;
#pragma unroll
            for (int j = 0; j < 8; j++) {
                float4 v = make_float4(0.f, 0.f, 0.f, 0.f);
                if (av[j]) v = *reinterpret_cast<const float4*>(xs + (size_t)ar[j] * IN_F + ac[j] * 4);
                pa[j] = pack_f4(v);
            }
#pragma unroll
            for (int j = 0; j < 8; j++) {
                float4 v = *reinterpret_cast<const float4*>(ws + (size_t)br[j] * OUT_F + bc[j] * 4);
                pb[j] = pack_f4(v);
            }
        }

        const __half* Ah = reinterpret_cast<const __half*>(smem + buf * TILE_STRIDE);
        const __half* Bh = reinterpret_cast<const __half*>(smem + buf * TILE_STRIDE + AH_BYTES);
#pragma unroll
        for (int ks = 0; ks < 4; ks++) {
            int k0 = ks * 16;
            wmma::fragment<wmma::matrix_b, 16, 16, 16, __half, wmma::row_major> bf[2];
#pragma unroll
            for (int nt = 0; nt < 2; nt++)
                wmma::load_matrix_sync(bf[nt], Bh + k0 * LDBH + warp_n * 32 + nt * 16, LDBH);
#pragma unroll
            for (int mt = 0; mt < 4; mt++) {
                wmma::fragment<wmma::matrix_a, 16, 16, 16, __half, wmma::row_major> af;
                wmma::load_matrix_sync(af, Ah + (warp_m * 64 + mt * 16) * LDAH + k0, LDAH);
                wmma::mma_sync(acc[mt][0], af, bf[0], acc[mt][0]);
                wmma::mma_sync(acc[mt][1], af, bf[1], acc[mt][1]);
            }
        }
    }

    // ---- epilogue (bias already in acc) ----
    if (cnt == BM) {
        // full tile: store fragments straight to gmem, no SMEM round-trip
#pragma unroll
        for (int mt = 0; mt < 4; mt++)
#pragma unroll
            for (int nt = 0; nt < 2; nt++)
                wmma::store_matrix_sync(
                    out + (size_t)(row0 + warp_m * 64 + mt * 16) * OUT_F
                        + ncol0 + warp_n * 32 + nt * 16,
                    acc[mt][nt], OUT_F, wmma::mem_row_major);
    } else {
        // partial tile: two 64-row half-passes through SMEM with row masking
        __syncthreads();   // all mma done before overwriting tiles region
        int c4 = tid & 31, rb = tid >> 5;
#pragma unroll
        for (int half = 0; half < 2; half++) {
            if (warp_m == half) {
#pragma unroll
                for (int mt = 0; mt < 4; mt++)
#pragma unroll
                    for (int nt = 0; nt < 2; nt++)
                        wmma::store_matrix_sync(
                            smf + (mt * 16) * LDE + warp_n * 32 + nt * 16,
                            acc[mt][nt], LDE, wmma::mem_row_major);
            }
            __syncthreads();
#pragma unroll
            for (int i = 0; i < 8; i++) {
                int rl = rb + i * 8;
                int r = half * 64 + rl;
                if (r < cnt)
                    *reinterpret_cast<float4*>(out + (size_t)(row0 + r) * OUT_F + ncol0 + c4 * 4) =
                        *reinterpret_cast<const float4*>(smf + rl * LDE + c4 * 4);
            }
            __syncthreads();
        }
    }
}

// ---------------- launcher ----------------
extern "C" void kernel_launch(void* const* d_in, const int* in_sizes, int n_in,
                              void* d_out, int out_size) {
    const float* x      = (const float*)d_in[0];
    const float* weight = (const float*)d_in[1];
    const float* bias   = (const float*)d_in[2];
    const int*   net_id = (const int*)d_in[3];
    // d_in[4] = slot_id (unused: points are sorted, slots contiguous within segments)
    float* out = (float*)d_out;

    cudaFuncSetAttribute(grouped_gemm_kernel,
                         cudaFuncAttributeMaxDynamicSharedMemorySize, SMEM_TOTAL);

    seg_kernel<<<NPOINTS / 256, 256>>>(net_id);
    grouped_gemm_kernel<<<NNET * SUBTILES * NCOLS, THREADS, SMEM_TOTAL>>>(x, weight, bias, out);
}

// round 10
// speedup vs baseline: 1.1034x; 1.0609x over previous
#include <cuda_runtime.h>
#include <cuda_fp16.h>
#include <mma.h>
#include <cstdint>
#include <cstring>

using namespace nvcuda;

#define NPOINTS   262144
#define NNET      512
#define IN_F      256
#define OUT_F     256
#define BM        128
#define BN        128
#define BK        32
#define N_CHUNKS  (IN_F / BK)        /* 8 */
#define SUBTILES  6                  /* ceil(768/128) */
#define NCOLS     (OUT_F / BN)       /* 2 */
#define THREADS   256
#define DEPTH     4                  /* cp.async pipeline stages */

// fp16 tile strides (halves), padded so LDSM phases spread banks; row strides stay 16B-multiples
#define LDAH  40    /* 32 + 8  -> 80B/row  */
#define LDBH  136   /* 128 + 8 -> 272B/row */
#define LDE   132   /* fp32 epilogue/bias stride */

// ---- dynamic SMEM layout (bytes) ----
#define AH_BYTES    (BM * LDAH * 2)              /* 10240 */
#define BH_BYTES    (BK * LDBH * 2)              /* 8704  */
#define TILE_STRIDE (AH_BYTES + BH_BYTES)        /* 18944, x DEPTH buffers */
#define BIAS_OFF    (DEPTH * TILE_STRIDE)        /* 75776 */
#define BIAS_BYTES  (16 * LDE * 4)               /* 8448  */
#define SMEM_TOTAL  (BIAS_OFF + BIAS_BYTES)      /* 84224; partial-epi (64*LDE*4) overlays tiles */

// ---- device scratch: pre-converted fp16 operands ----
__device__ __align__(16) __half g_xh[(size_t)NPOINTS * IN_F];          /* 134 MB */
__device__ __align__(16) __half g_wh[(size_t)NNET * IN_F * OUT_F];     /* 67 MB  */
__device__ int g_seg[NNET];

// ---------------- helpers ----------------
__device__ __forceinline__ uint32_t smem_u32(const void* p) {
    uint32_t a;
    asm("{ .reg .u64 t; cvta.to.shared.u64 t, %1; cvt.u32.u64 %0, t; }" : "=r"(a) : "l"(p));
    return a;
}
__device__ __forceinline__ void cp_async16(uint32_t dst, const void* src, bool valid) {
    int sz = valid ? 16 : 0;   // ignore-src: zero-fill when invalid
    asm volatile("cp.async.cg.shared.global [%0], [%1], 16, %2;"
                 :: "r"(dst), "l"(src), "r"(sz));
}
__device__ __forceinline__ void cp_commit() {
    asm volatile("cp.async.commit_group;" ::: "memory");
}
template <int N>
__device__ __forceinline__ void cp_wait() {
    asm volatile("cp.async.wait_group %0;" :: "n"(N) : "memory");
}
__device__ __forceinline__ uint32_t h2u(__half2 h) {
    uint32_t u; memcpy(&u, &h, 4); return u;
}

// ---------------- kernel 0: segment starts ----------------
__global__ void seg_kernel(const int* __restrict__ net_id) {
    int p = blockIdx.x * blockDim.x + threadIdx.x;
    if (p >= NPOINTS) return;
    int nid = net_id[p];
    if (p == 0 || net_id[p - 1] != nid) g_seg[nid] = p;
}

// ---------------- kernels 1-2: fp32 -> fp16 streaming converts ----------------
__global__ void __launch_bounds__(256) cvt_x_kernel(const float* __restrict__ x) {
    size_t i = (size_t)(blockIdx.x * 256 + threadIdx.x) * 8;   // 8 floats/thread
    float4 v0 = *reinterpret_cast<const float4*>(x + i);
    float4 v1 = *reinterpret_cast<const float4*>(x + i + 4);
    uint4 p;
    p.x = h2u(__float22half2_rn(make_float2(v0.x, v0.y)));
    p.y = h2u(__float22half2_rn(make_float2(v0.z, v0.w)));
    p.z = h2u(__float22half2_rn(make_float2(v1.x, v1.y)));
    p.w = h2u(__float22half2_rn(make_float2(v1.z, v1.w)));
    *reinterpret_cast<uint4*>(g_xh + i) = p;
}
__global__ void __launch_bounds__(256) cvt_w_kernel(const float* __restrict__ w) {
    size_t i = (size_t)(blockIdx.x * 256 + threadIdx.x) * 8;
    float4 v0 = *reinterpret_cast<const float4*>(w + i);
    float4 v1 = *reinterpret_cast<const float4*>(w + i + 4);
    uint4 p;
    p.x = h2u(__float22half2_rn(make_float2(v0.x, v0.y)));
    p.y = h2u(__float22half2_rn(make_float2(v0.z, v0.w)));
    p.z = h2u(__float22half2_rn(make_float2(v1.x, v1.y)));
    p.w = h2u(__float22half2_rn(make_float2(v1.z, v1.w)));
    *reinterpret_cast<uint4*>(g_wh + i) = p;
}

// -------- kernel 3: pure-fp16 grouped GEMM, 4-stage cp.async pipeline --------
__global__ void __launch_bounds__(THREADS, 2)
grouped_gemm_kernel(const float* __restrict__ bias, float* __restrict__ out) {
    int bx   = blockIdx.x;
    int ncol = bx & (NCOLS - 1);
    int sub  = (bx >> 1) % SUBTILES;
    int n    = bx / (SUBTILES * NCOLS);

    int s0 = g_seg[n];
    int s1 = (n == NNET - 1) ? NPOINTS : g_seg[n + 1];
    int row0 = s0 + sub * BM;
    int cnt = s1 - row0;
    if (cnt <= 0) return;
    if (cnt > BM) cnt = BM;
    int ncol0 = ncol * BN;

    extern __shared__ char smem[];
    float* smf = reinterpret_cast<float*>(smem);
    uint32_t smem_base = smem_u32(smem);

    int tid = threadIdx.x;
    int wid = tid >> 5;
    int warp_m = wid >> 2;                // 0..1 -> 64-row slab
    int warp_n = wid & 3;                 // 0..3 -> 32-col slab

    const __half* xh = g_xh + (size_t)row0 * IN_F;
    const __half* wh = g_wh + (size_t)n * IN_F * OUT_F + ncol0;   // [in][out] fp16

    // per-thread cp.async coordinates: A = 512 16B-chunks, B = 512 16B-chunks -> 2+2 per thread
    int arow[2], acol[2]; bool av[2]; uint32_t adst[2];
    int brow[2], bcol[2]; uint32_t bdst[2];
#pragma unroll
    for (int j = 0; j < 2; j++) {
        int idx = tid + j * THREADS;
        arow[j] = idx >> 2; acol[j] = idx & 3;         // A: 128 rows x 4 chunks (64B data/row)
        av[j] = arow[j] < cnt;
        adst[j] = (uint32_t)(arow[j] * (LDAH * 2) + acol[j] * 16);
        brow[j] = idx >> 4; bcol[j] = idx & 15;        // B: 32 rows x 16 chunks (256B data/row)
        bdst[j] = (uint32_t)(AH_BYTES + brow[j] * (LDBH * 2) + bcol[j] * 16);
    }

    // issue one stage of cp.async (A chunk + B chunk for K-slice c)
    auto issue_stage = [&](int c) {
        uint32_t base = smem_base + (c & (DEPTH - 1)) * TILE_STRIDE;
        int k0 = c * BK;
#pragma unroll
        for (int j = 0; j < 2; j++)
            cp_async16(base + adst[j], xh + (size_t)arow[j] * IN_F + k0 + acol[j] * 8, av[j]);
#pragma unroll
        for (int j = 0; j < 2; j++)
            cp_async16(base + bdst[j], wh + (size_t)(k0 + brow[j]) * OUT_F + bcol[j] * 8, true);
        cp_commit();
    };

    // prologue: 3 stages in flight + bias tile
    issue_stage(0); issue_stage(1); issue_stage(2);
    {
        int rowb = tid >> 4, colb = (tid & 15) * 8;
        const float* bsrc = bias + (size_t)n * OUT_F + ncol0 + colb;
        float* dst = smf + (BIAS_OFF / 4) + rowb * LDE + colb;
        *reinterpret_cast<float4*>(dst)     = *reinterpret_cast<const float4*>(bsrc);
        *reinterpret_cast<float4*>(dst + 4) = *reinterpret_cast<const float4*>(bsrc + 4);
    }
    __syncthreads();   // bias visible

    // accumulators preloaded with bias
    wmma::fragment<wmma::accumulator, 16, 16, 16, float> acc[4][2];
#pragma unroll
    for (int nt = 0; nt < 2; nt++) {
        wmma::load_matrix_sync(acc[0][nt],
                               smf + (BIAS_OFF / 4) + warp_n * 32 + nt * 16,
                               LDE, wmma::mem_row_major);
#pragma unroll
        for (int mt = 1; mt < 4; mt++) acc[mt][nt] = acc[0][nt];
    }

    // ---- mainloop: one __syncthreads per chunk; fetch 3 chunks ahead ----
    for (int c = 0; c < N_CHUNKS; c++) {
        cp_wait<2>();       // group c complete (c+1, c+2 still pending)
        __syncthreads();    // all warps see tiles[c]; all warps done reading buf (c+3)&3 (iter c-1)

        if (c + 3 < N_CHUNKS) issue_stage(c + 3);   // fire-and-forget, lands 3 chunks later

        const __half* Ah = reinterpret_cast<const __half*>(smem + (c & (DEPTH - 1)) * TILE_STRIDE);
        const __half* Bh = reinterpret_cast<const __half*>(smem + (c & (DEPTH - 1)) * TILE_STRIDE + AH_BYTES);
#pragma unroll
        for (int ks = 0; ks < 2; ks++) {
            int k0 = ks * 16;
            wmma::fragment<wmma::matrix_b, 16, 16, 16, __half, wmma::row_major> bf[2];
#pragma unroll
            for (int nt = 0; nt < 2; nt++)
                wmma::load_matrix_sync(bf[nt], Bh + k0 * LDBH + warp_n * 32 + nt * 16, LDBH);
#pragma unroll
            for (int mt = 0; mt < 4; mt++) {
                wmma::fragment<wmma::matrix_a, 16, 16, 16, __half, wmma::row_major> af;
                wmma::load_matrix_sync(af, Ah + (warp_m * 64 + mt * 16) * LDAH + k0, LDAH);
                wmma::mma_sync(acc[mt][0], af, bf[0], acc[mt][0]);
                wmma::mma_sync(acc[mt][1], af, bf[1], acc[mt][1]);
            }
        }
    }

    // ---- epilogue (bias already in acc) ----
    if (cnt == BM) {
#pragma unroll
        for (int mt = 0; mt < 4; mt++)
#pragma unroll
            for (int nt = 0; nt < 2; nt++)
                wmma::store_matrix_sync(
                    out + (size_t)(row0 + warp_m * 64 + mt * 16) * OUT_F
                        + ncol0 + warp_n * 32 + nt * 16,
                    acc[mt][nt], OUT_F, wmma::mem_row_major);
    } else {
        __syncthreads();   // all mma done before overwriting tile buffers
        int c4 = tid & 31, rb = tid >> 5;
#pragma unroll
        for (int half = 0; half < 2; half++) {
            if (warp_m == half) {
#pragma unroll
                for (int mt = 0; mt < 4; mt++)
#pragma unroll
                    for (int nt = 0; nt < 2; nt++)
                        wmma::store_matrix_sync(
                            smf + (mt * 16) * LDE + warp_n * 32 + nt * 16,
                            acc[mt][nt], LDE, wmma::mem_row_major);
            }
            __syncthreads();
#pragma unroll
            for (int i = 0; i < 8; i++) {
                int rl = rb + i * 8;
                int r = half * 64 + rl;
                if (r < cnt)
                    *reinterpret_cast<float4*>(out + (size_t)(row0 + r) * OUT_F + ncol0 + c4 * 4) =
                        *reinterpret_cast<const float4*>(smf + rl * LDE + c4 * 4);
            }
            __syncthreads();
        }
    }
}

// ---------------- launcher ----------------
extern "C" void kernel_launch(void* const* d_in, const int* in_sizes, int n_in,
                              void* d_out, int out_size) {
    const float* x      = (const float*)d_in[0];
    const float* weight = (const float*)d_in[1];
    const float* bias   = (const float*)d_in[2];
    const int*   net_id = (const int*)d_in[3];
    // d_in[4] = slot_id (unused: points sorted, slots contiguous within segments)
    float* out = (float*)d_out;

    cudaFuncSetAttribute(grouped_gemm_kernel,
                         cudaFuncAttributeMaxDynamicSharedMemorySize, SMEM_TOTAL);

    seg_kernel<<<NPOINTS / 256, 256>>>(net_id);
    cvt_x_kernel<<<(int)((size_t)NPOINTS * IN_F / 8 / 256), 256>>>(x);
    cvt_w_kernel<<<(int)((size_t)NNET * IN_F * OUT_F / 8 / 256), 256>>>(weight);
    grouped_gemm_kernel<<<NNET * SUBTILES * NCOLS, THREADS, SMEM_TOTAL>>>(bias, out);
}

// round 15
// speedup vs baseline: 1.2008x; 1.0883x over previous
#include <cuda_runtime.h>
#include <cuda_fp16.h>
#include <mma.h>
#include <cstdint>
#include <cstring>

using namespace nvcuda;

#define NPOINTS   262144
#define NNET      512
#define IN_F      256
#define OUT_F     256
#define BM        128
#define BN        128
#define BK        32
#define N_CHUNKS  (IN_F / BK)        /* 8 */
#define SUBTILES  6                  /* ceil(768/128) */
#define NCOLS     (OUT_F / BN)       /* 2 */
#define THREADS   256
#define RINGD     3                  /* cp.async ring depth */

// fp16 tile strides (halves), conflict-free for LDSM phases
#define LDAH  40    /* 32 + 8  -> 80B/row  */
#define LDBH  136   /* 128 + 8 -> 272B/row */
#define LDE   132   /* fp32 epilogue/bias stride */

// ---- dynamic SMEM layout (bytes) ----
#define A32_ROWB    144                          /* fp32 A staging row: 128B data + 16B pad */
#define A32S        (BM * A32_ROWB)              /* 18432 per stage */
#define A32_OFF     0                            /* ring of RINGD */
#define BH_OFF      (A32_OFF + RINGD * A32S)     /* 55296 */
#define BH_BYTES    (BK * LDBH * 2)              /* 8704 per stage, ring of RINGD */
#define AH_OFF      (BH_OFF + RINGD * BH_BYTES)  /* 81408 */
#define AH_BYTES    (BM * LDAH * 2)              /* 10240, x2 buffers */
#define BIAS_OFF    (AH_OFF + 2 * AH_BYTES)      /* 101888 */
#define BIAS_BYTES  (16 * LDE * 4)               /* 8448 */
#define SMEM_TOTAL  (BIAS_OFF + BIAS_BYTES)      /* 110336 -> 2 CTAs/SM fits 227KB */

// ---- device scratch: pre-converted fp16 W only ----
__device__ __align__(16) __half g_wh[(size_t)NNET * IN_F * OUT_F];     /* 67 MB */
__device__ int g_seg[NNET];

// ---------------- helpers ----------------
__device__ __forceinline__ uint32_t smem_u32(const void* p) {
    uint32_t a;
    asm("{ .reg .u64 t; cvta.to.shared.u64 t, %1; cvt.u32.u64 %0, t; }" : "=r"(a) : "l"(p));
    return a;
}
__device__ __forceinline__ void cp_async16(uint32_t dst, const void* src, bool valid) {
    int sz = valid ? 16 : 0;   // ignore-src: zero-fill when invalid
    asm volatile("cp.async.cg.shared.global [%0], [%1], 16, %2;"
                 :: "r"(dst), "l"(src), "r"(sz));
}
__device__ __forceinline__ void cp_commit() {
    asm volatile("cp.async.commit_group;" ::: "memory");
}
template <int N>
__device__ __forceinline__ void cp_wait() {
    asm volatile("cp.async.wait_group %0;" :: "n"(N) : "memory");
}
__device__ __forceinline__ uint32_t h2u(__half2 h) {
    uint32_t u; memcpy(&u, &h, 4); return u;
}

// ---------------- kernel 0: segment starts ----------------
__global__ void seg_kernel(const int* __restrict__ net_id) {
    int p = blockIdx.x * blockDim.x + threadIdx.x;
    if (p >= NPOINTS) return;
    int nid = net_id[p];
    if (p == 0 || net_id[p - 1] != nid) g_seg[nid] = p;
}

// ---------------- kernel 1: W fp32 -> fp16 streaming convert ----------------
__global__ void __launch_bounds__(256) cvt_w_kernel(const float* __restrict__ w) {
    size_t i = (size_t)(blockIdx.x * 256 + threadIdx.x) * 8;
    float4 v0 = *reinterpret_cast<const float4*>(w + i);
    float4 v1 = *reinterpret_cast<const float4*>(w + i + 4);
    uint4 p;
    p.x = h2u(__float22half2_rn(make_float2(v0.x, v0.y)));
    p.y = h2u(__float22half2_rn(make_float2(v0.z, v0.w)));
    p.z = h2u(__float22half2_rn(make_float2(v1.x, v1.y)));
    p.w = h2u(__float22half2_rn(make_float2(v1.z, v1.w)));
    *reinterpret_cast<uint4*>(g_wh + i) = p;
}

// -------- kernel 2: grouped GEMM — fp32 x via cp.async ring, in-kernel A convert --------
__global__ void __launch_bounds__(THREADS, 2)
grouped_gemm_kernel(const float* __restrict__ x, const float* __restrict__ bias,
                    float* __restrict__ out) {
    int bx   = blockIdx.x;
    int ncol = bx & (NCOLS - 1);
    int sub  = (bx >> 1) % SUBTILES;
    int n    = bx / (SUBTILES * NCOLS);

    int s0 = g_seg[n];
    int s1 = (n == NNET - 1) ? NPOINTS : g_seg[n + 1];
    int row0 = s0 + sub * BM;
    int cnt = s1 - row0;
    if (cnt <= 0) return;
    if (cnt > BM) cnt = BM;
    int ncol0 = ncol * BN;

    extern __shared__ char smem[];
    float* smf = reinterpret_cast<float*>(smem);
    uint32_t smem_base = smem_u32(smem);

    int tid = threadIdx.x;
    int wid = tid >> 5;
    int warp_m = wid >> 2;                // 0..1 -> 64-row slab
    int warp_n = wid & 3;                 // 0..3 -> 32-col slab

    const float* xs = x + (size_t)row0 * IN_F;
    const __half* wh = g_wh + (size_t)n * IN_F * OUT_F + ncol0;   // [in][out] fp16

    // cp.async coordinates
    // A fp32 chunk: 128 rows x 8 x 16B -> 1024 chunks -> 4/thread
    int ar[4], ac[4]; bool av[4]; uint32_t adst[4];
    // B fp16 chunk: 32 rows x 16 x 16B -> 512 chunks -> 2/thread
    int brow[2], bcol[2]; uint32_t bdst[2];
#pragma unroll
    for (int j = 0; j < 4; j++) {
        int idx = tid + j * THREADS;
        ar[j] = idx >> 3; ac[j] = idx & 7;
        av[j] = ar[j] < cnt;
        adst[j] = (uint32_t)(A32_OFF + ar[j] * A32_ROWB + ac[j] * 16);
    }
#pragma unroll
    for (int j = 0; j < 2; j++) {
        int idx = tid + j * THREADS;
        brow[j] = idx >> 4; bcol[j] = idx & 15;
        bdst[j] = (uint32_t)(BH_OFF + brow[j] * (LDBH * 2) + bcol[j] * 16);
    }

    auto issue_stage = [&](int c, int s3) {   // s3 = c % RINGD
        int k0 = c * BK;
#pragma unroll
        for (int j = 0; j < 4; j++)
            cp_async16(smem_base + s3 * A32S + adst[j],
                       xs + (size_t)ar[j] * IN_F + k0 + ac[j] * 4, av[j]);
#pragma unroll
        for (int j = 0; j < 2; j++)
            cp_async16(smem_base + s3 * BH_BYTES + bdst[j],
                       wh + (size_t)(k0 + brow[j]) * OUT_F + bcol[j] * 8, true);
        cp_commit();
    };

    // prologue: 2 stages in flight + bias tile
    issue_stage(0, 0); issue_stage(1, 1);
    {
        int rowb = tid >> 4, colb = (tid & 15) * 8;
        const float* bsrc = bias + (size_t)n * OUT_F + ncol0 + colb;
        float* dst = smf + (BIAS_OFF / 4) + rowb * LDE + colb;
        *reinterpret_cast<float4*>(dst)     = *reinterpret_cast<const float4*>(bsrc);
        *reinterpret_cast<float4*>(dst + 4) = *reinterpret_cast<const float4*>(bsrc + 4);
    }
    __syncthreads();   // bias visible

    wmma::fragment<wmma::accumulator, 16, 16, 16, float> acc[4][2];
#pragma unroll
    for (int nt = 0; nt < 2; nt++) {
        wmma::load_matrix_sync(acc[0][nt],
                               smf + (BIAS_OFF / 4) + warp_n * 32 + nt * 16,
                               LDE, wmma::mem_row_major);
#pragma unroll
        for (int mt = 1; mt < 4; mt++) acc[mt][nt] = acc[0][nt];
    }

    // convert-pass coordinates: thread -> (row = tid/2, 16-float half)
    int crr = tid >> 1, crh = tid & 1;
    const float* cvt_src0 = smf + (A32_OFF / 4) + crr * (A32_ROWB / 4) + crh * 16;
    uint32_t* cvt_dst0 = reinterpret_cast<uint32_t*>(smem + AH_OFF + (crr * LDAH + crh * 16) * 2);

    int s3 = 0;   // running c % RINGD
    for (int c = 0; c < N_CHUNKS; c++) {
        // TAIL-SAFE WAIT: at c == N_CHUNKS-1 the newest pending group IS group c,
        // so wait_group 1 would let us read an in-flight tile (R11's 4.6e-3 bug).
        if (c == N_CHUNKS - 1) cp_wait<0>(); else cp_wait<1>();
        __syncthreads();    // staging[s3] + Bh[s3] visible to all; Ah[c&1] free (mma(c-1) done)

        int s3n = s3 + 2; if (s3n >= RINGD) s3n -= RINGD;
        if (c + 2 < N_CHUNKS) issue_stage(c + 2, s3n);   // buffer (c+2)%3 free: last read at iter c-1

        // ---- A convert: fp32 staging[s3] -> fp16 Ah[c&1] ----
        {
            const float* src = cvt_src0 + s3 * (A32S / 4);
            float4 v0 = *reinterpret_cast<const float4*>(src);
            float4 v1 = *reinterpret_cast<const float4*>(src + 4);
            float4 v2 = *reinterpret_cast<const float4*>(src + 8);
            float4 v3 = *reinterpret_cast<const float4*>(src + 12);
            uint4 p0, p1;
            p0.x = h2u(__float22half2_rn(make_float2(v0.x, v0.y)));
            p0.y = h2u(__float22half2_rn(make_float2(v0.z, v0.w)));
            p0.z = h2u(__float22half2_rn(make_float2(v1.x, v1.y)));
            p0.w = h2u(__float22half2_rn(make_float2(v1.z, v1.w)));
            p1.x = h2u(__float22half2_rn(make_float2(v2.x, v2.y)));
            p1.y = h2u(__float22half2_rn(make_float2(v2.z, v2.w)));
            p1.z = h2u(__float22half2_rn(make_float2(v3.x, v3.y)));
            p1.w = h2u(__float22half2_rn(make_float2(v3.z, v3.w)));
            uint32_t* dst = cvt_dst0 + (c & 1) * (AH_BYTES / 4);
            *reinterpret_cast<uint4*>(dst)     = p0;
            *reinterpret_cast<uint4*>(dst + 4) = p1;
        }
        __syncthreads();    // Ah[c&1] ready

        const __half* Ah = reinterpret_cast<const __half*>(smem + AH_OFF + (c & 1) * AH_BYTES);
        const __half* Bh = reinterpret_cast<const __half*>(smem + BH_OFF + s3 * BH_BYTES);
#pragma unroll
        for (int ks = 0; ks < 2; ks++) {
            int k0 = ks * 16;
            wmma::fragment<wmma::matrix_b, 16, 16, 16, __half, wmma::row_major> bf[2];
#pragma unroll
            for (int nt = 0; nt < 2; nt++)
                wmma::load_matrix_sync(bf[nt], Bh + k0 * LDBH + warp_n * 32 + nt * 16, LDBH);
#pragma unroll
            for (int mt = 0; mt < 4; mt++) {
                wmma::fragment<wmma::matrix_a, 16, 16, 16, __half, wmma::row_major> af;
                wmma::load_matrix_sync(af, Ah + (warp_m * 64 + mt * 16) * LDAH + k0, LDAH);
                wmma::mma_sync(acc[mt][0], af, bf[0], acc[mt][0]);
                wmma::mma_sync(acc[mt][1], af, bf[1], acc[mt][1]);
            }
        }
        if (++s3 == RINGD) s3 = 0;
    }

    // ---- epilogue (bias already in acc) ----
    if (cnt == BM) {
#pragma unroll
        for (int mt = 0; mt < 4; mt++)
#pragma unroll
            for (int nt = 0; nt < 2; nt++)
                wmma::store_matrix_sync(
                    out + (size_t)(row0 + warp_m * 64 + mt * 16) * OUT_F
                        + ncol0 + warp_n * 32 + nt * 16,
                    acc[mt][nt], OUT_F, wmma::mem_row_major);
    } else {
        __syncthreads();   // all mma done before overwriting SMEM front
        int c4 = tid & 31, rb = tid >> 5;
#pragma unroll
        for (int half = 0; half < 2; half++) {
            if (warp_m == half) {
#pragma unroll
                for (int mt = 0; mt < 4; mt++)
#pragma unroll
                    for (int nt = 0; nt < 2; nt++)
                        wmma::store_matrix_sync(
                            smf + (mt * 16) * LDE + warp_n * 32 + nt * 16,
                            acc[mt][nt], LDE, wmma::mem_row_major);
            }
            __syncthreads();
#pragma unroll
            for (int i = 0; i < 8; i++) {
                int rl = rb + i * 8;
                int r = half * 64 + rl;
                if (r < cnt)
                    *reinterpret_cast<float4*>(out + (size_t)(row0 + r) * OUT_F + ncol0 + c4 * 4) =
                        *reinterpret_cast<const float4*>(smf + rl * LDE + c4 * 4);
            }
            __syncthreads();
        }
    }
}

// ---------------- launcher ----------------
extern "C" void kernel_launch(void* const* d_in, const int* in_sizes, int n_in,
                              void* d_out, int out_size) {
    const float* x      = (const float*)d_in[0];
    const float* weight = (const float*)d_in[1];
    const float* bias   = (const float*)d_in[2];
    const int*   net_id = (const int*)d_in[3];
    // d_in[4] = slot_id (unused: points sorted, slots contiguous within segments)
    float* out = (float*)d_out;

    cudaFuncSetAttribute(grouped_gemm_kernel,
                         cudaFuncAttributeMaxDynamicSharedMemorySize, SMEM_TOTAL);

    seg_kernel<<<NPOINTS / 256, 256>>>(net_id);
    cvt_w_kernel<<<(int)((size_t)NNET * IN_F * OUT_F / 8 / 256), 256>>>(weight);
    grouped_gemm_kernel<<<NNET * SUBTILES * NCOLS, THREADS, SMEM_TOTAL>>>(x, bias, out);
}

// round 16
// speedup vs baseline: 1.2027x; 1.0016x over previous
#include <cuda_runtime.h>
#include <cuda_fp16.h>
#include <mma.h>
#include <cstdint>
#include <cstring>

using namespace nvcuda;

#define NPOINTS   262144
#define NNET      512
#define IN_F      256
#define OUT_F     256
#define BM        128
#define BN        128
#define BK        32
#define N_CHUNKS  (IN_F / BK)        /* 8 */
#define SUBTILES  6                  /* ceil(768/128) */
#define NCOLS     (OUT_F / BN)       /* 2 */
#define THREADS   256
#define RA        3                  /* fp32 A staging ring depth */
#define RB        4                  /* fp16 B tile ring depth (power of 2) */

// fp16 tile strides (halves), conflict-free for LDSM phases
#define LDAH  40    /* 32 + 8  -> 80B/row  */
#define LDBH  136   /* 128 + 8 -> 272B/row */
#define LDE   132   /* fp32 epilogue/bias stride */

// ---- dynamic SMEM layout (bytes) ----
#define A32_ROWB    144                          /* fp32 A staging row: 128B data + 16B pad */
#define A32S        (BM * A32_ROWB)              /* 18432 per stage */
#define A32_OFF     0                            /* ring of RA */
#define BH_OFF      (A32_OFF + RA * A32S)        /* 55296 */
#define BH_BYTES    (BK * LDBH * 2)              /* 8704 per stage, ring of RB */
#define AH_OFF      (BH_OFF + RB * BH_BYTES)     /* 90112 */
#define AH_BYTES    (BM * LDAH * 2)              /* 10240, x2 buffers (contiguous) */
#define BIAS_OFF    (AH_OFF + AH_BYTES)          /* 100352: OVERLAYS Ah[1] — bias dead after
                                                    acc preload, Ah[1] first written after it */
#define SMEM_TOTAL  (AH_OFF + 2 * AH_BYTES)      /* 110592 -> 2 CTAs/SM (113664 cap) */

// ---- device scratch: pre-converted fp16 W only ----
__device__ __align__(16) __half g_wh[(size_t)NNET * IN_F * OUT_F];     /* 67 MB */
__device__ int g_seg[NNET];

// ---------------- helpers ----------------
__device__ __forceinline__ uint32_t smem_u32(const void* p) {
    uint32_t a;
    asm("{ .reg .u64 t; cvta.to.shared.u64 t, %1; cvt.u32.u64 %0, t; }" : "=r"(a) : "l"(p));
    return a;
}
__device__ __forceinline__ void cp_async16(uint32_t dst, const void* src, bool valid) {
    int sz = valid ? 16 : 0;   // ignore-src: zero-fill when invalid
    asm volatile("cp.async.cg.shared.global [%0], [%1], 16, %2;"
                 :: "r"(dst), "l"(src), "r"(sz));
}
__device__ __forceinline__ void cp_commit() {
    asm volatile("cp.async.commit_group;" ::: "memory");
}
template <int N>
__device__ __forceinline__ void cp_wait() {
    asm volatile("cp.async.wait_group %0;" :: "n"(N) : "memory");
}
__device__ __forceinline__ uint32_t h2u(__half2 h) {
    uint32_t u; memcpy(&u, &h, 4); return u;
}

// ---------------- kernel 0: segment starts ----------------
__global__ void seg_kernel(const int* __restrict__ net_id) {
    int p = blockIdx.x * blockDim.x + threadIdx.x;
    if (p >= NPOINTS) return;
    int nid = net_id[p];
    if (p == 0 || net_id[p - 1] != nid) g_seg[nid] = p;
}

// ---------------- kernel 1: W fp32 -> fp16 streaming convert ----------------
__global__ void __launch_bounds__(256) cvt_w_kernel(const float* __restrict__ w) {
    size_t i = (size_t)(blockIdx.x * 256 + threadIdx.x) * 8;
    float4 v0 = *reinterpret_cast<const float4*>(w + i);
    float4 v1 = *reinterpret_cast<const float4*>(w + i + 4);
    uint4 p;
    p.x = h2u(__float22half2_rn(make_float2(v0.x, v0.y)));
    p.y = h2u(__float22half2_rn(make_float2(v0.z, v0.w)));
    p.z = h2u(__float22half2_rn(make_float2(v1.x, v1.y)));
    p.w = h2u(__float22half2_rn(make_float2(v1.z, v1.w)));
    *reinterpret_cast<uint4*>(g_wh + i) = p;
}

// -------- kernel 2: grouped GEMM — pipelined in-kernel A convert, 1 barrier/chunk --------
__global__ void __launch_bounds__(THREADS, 2)
grouped_gemm_kernel(const float* __restrict__ x, const float* __restrict__ bias,
                    float* __restrict__ out) {
    int bx   = blockIdx.x;
    int ncol = bx & (NCOLS - 1);
    int sub  = (bx >> 1) % SUBTILES;
    int n    = bx / (SUBTILES * NCOLS);

    int s0 = g_seg[n];
    int s1 = (n == NNET - 1) ? NPOINTS : g_seg[n + 1];
    int row0 = s0 + sub * BM;
    int cnt = s1 - row0;
    if (cnt <= 0) return;
    if (cnt > BM) cnt = BM;
    int ncol0 = ncol * BN;

    extern __shared__ char smem[];
    float* smf = reinterpret_cast<float*>(smem);
    uint32_t smem_base = smem_u32(smem);

    int tid = threadIdx.x;
    int wid = tid >> 5;
    int warp_m = wid >> 2;                // 0..1 -> 64-row slab
    int warp_n = wid & 3;                 // 0..3 -> 32-col slab

    const float* xs = x + (size_t)row0 * IN_F;
    const __half* wh = g_wh + (size_t)n * IN_F * OUT_F + ncol0;   // [in][out] fp16

    // cp.async coordinates
    int ar[4], ac[4]; bool av[4]; uint32_t adst[4];   // A fp32: 128 rows x 8 x16B -> 4/thread
    int brow[2], bcol[2]; uint32_t bdst[2];           // B fp16: 32 rows x 16 x16B -> 2/thread
#pragma unroll
    for (int j = 0; j < 4; j++) {
        int idx = tid + j * THREADS;
        ar[j] = idx >> 3; ac[j] = idx & 7;
        av[j] = ar[j] < cnt;
        adst[j] = (uint32_t)(A32_OFF + ar[j] * A32_ROWB + ac[j] * 16);
    }
#pragma unroll
    for (int j = 0; j < 2; j++) {
        int idx = tid + j * THREADS;
        brow[j] = idx >> 4; bcol[j] = idx & 15;
        bdst[j] = (uint32_t)(BH_OFF + brow[j] * (LDBH * 2) + bcol[j] * 16);
    }

    auto issue_stage = [&](int c) {
        int sA = c % RA, sB = c & (RB - 1);
        int k0 = c * BK;
#pragma unroll
        for (int j = 0; j < 4; j++)
            cp_async16(smem_base + sA * A32S + adst[j],
                       xs + (size_t)ar[j] * IN_F + k0 + ac[j] * 4, av[j]);
#pragma unroll
        for (int j = 0; j < 2; j++)
            cp_async16(smem_base + sB * BH_BYTES + bdst[j],
                       wh + (size_t)(k0 + brow[j]) * OUT_F + bcol[j] * 8, true);
        cp_commit();
    };

    // convert-pass coordinates: thread -> (row = tid/2, 16-float half)
    int crr = tid >> 1, crh = tid & 1;
    const float* cvt_src0 = smf + (A32_OFF / 4) + crr * (A32_ROWB / 4) + crh * 16;
    uint32_t* cvt_dst0 = reinterpret_cast<uint32_t*>(smem + AH_OFF + (crr * LDAH + crh * 16) * 2);

    auto convert_chunk = [&](int c) {   // fp32 staging[c%RA] -> fp16 Ah[c&1]
        const float* src = cvt_src0 + (c % RA) * (A32S / 4);
        float4 v0 = *reinterpret_cast<const float4*>(src);
        float4 v1 = *reinterpret_cast<const float4*>(src + 4);
        float4 v2 = *reinterpret_cast<const float4*>(src + 8);
        float4 v3 = *reinterpret_cast<const float4*>(src + 12);
        uint4 p0, p1;
        p0.x = h2u(__float22half2_rn(make_float2(v0.x, v0.y)));
        p0.y = h2u(__float22half2_rn(make_float2(v0.z, v0.w)));
        p0.z = h2u(__float22half2_rn(make_float2(v1.x, v1.y)));
        p0.w = h2u(__float22half2_rn(make_float2(v1.z, v1.w)));
        p1.x = h2u(__float22half2_rn(make_float2(v2.x, v2.y)));
        p1.y = h2u(__float22half2_rn(make_float2(v2.z, v2.w)));
        p1.z = h2u(__float22half2_rn(make_float2(v3.x, v3.y)));
        p1.w = h2u(__float22half2_rn(make_float2(v3.z, v3.w)));
        uint32_t* dst = cvt_dst0 + (c & 1) * (AH_BYTES / 4);
        *reinterpret_cast<uint4*>(dst)     = p0;
        *reinterpret_cast<uint4*>(dst + 4) = p1;
    };

    // ---- prologue: 3 stages in flight, bias tile, acc preload, convert(0) ----
    issue_stage(0); issue_stage(1); issue_stage(2);
    {
        int rowb = tid >> 4, colb = (tid & 15) * 8;
        const float* bsrc = bias + (size_t)n * OUT_F + ncol0 + colb;
        float* dst = smf + (BIAS_OFF / 4) + rowb * LDE + colb;
        *reinterpret_cast<float4*>(dst)     = *reinterpret_cast<const float4*>(bsrc);
        *reinterpret_cast<float4*>(dst + 4) = *reinterpret_cast<const float4*>(bsrc + 4);
    }
    cp_wait<2>();      // group 0 done
    __syncthreads();   // staging0 + Bh0 + bias visible

    wmma::fragment<wmma::accumulator, 16, 16, 16, float> acc[4][2];
#pragma unroll
    for (int nt = 0; nt < 2; nt++) {
        wmma::load_matrix_sync(acc[0][nt],
                               smf + (BIAS_OFF / 4) + warp_n * 32 + nt * 16,
                               LDE, wmma::mem_row_major);
#pragma unroll
        for (int mt = 1; mt < 4; mt++) acc[mt][nt] = acc[0][nt];
    }
    convert_chunk(0);  // Ah[0]; bias (Ah[1] overlay) already consumed by all threads? no —
                       // consumed above, and Ah[1] is first WRITTEN at iter 0 AFTER its sync ✓

    // ---- mainloop: ONE barrier per chunk; convert runs one chunk ahead of mma ----
    for (int c = 0; c < N_CHUNKS; c++) {
        // group (c+1) must be complete for convert(c+1). While a younger group is
        // pending, wait<1> suffices; at the tail the needed group IS the newest -> wait<0>.
        if (c >= N_CHUNKS - 2) cp_wait<0>(); else cp_wait<1>();
        __syncthreads();   // publishes convert(c)'s Ah[c&1]; retires reads of ring buffers
                           // about to be overwritten (staging[(c+3)%RA], Bh[(c+3)%RB])

        if (c + 3 < N_CHUNKS) issue_stage(c + 3);
        if (c + 1 < N_CHUNKS) convert_chunk(c + 1);   // fills Ah[(c+1)&1] under mma(c)

        const __half* Ah = reinterpret_cast<const __half*>(smem + AH_OFF + (c & 1) * AH_BYTES);
        const __half* Bh = reinterpret_cast<const __half*>(smem + BH_OFF + (c & (RB - 1)) * BH_BYTES);
#pragma unroll
        for (int ks = 0; ks < 2; ks++) {
            int k0 = ks * 16;
            wmma::fragment<wmma::matrix_b, 16, 16, 16, __half, wmma::row_major> bf[2];
#pragma unroll
            for (int nt = 0; nt < 2; nt++)
                wmma::load_matrix_sync(bf[nt], Bh + k0 * LDBH + warp_n * 32 + nt * 16, LDBH);
#pragma unroll
            for (int mt = 0; mt < 4; mt++) {
                wmma::fragment<wmma::matrix_a, 16, 16, 16, __half, wmma::row_major> af;
                wmma::load_matrix_sync(af, Ah + (warp_m * 64 + mt * 16) * LDAH + k0, LDAH);
                wmma::mma_sync(acc[mt][0], af, bf[0], acc[mt][0]);
                wmma::mma_sync(acc[mt][1], af, bf[1], acc[mt][1]);
            }
        }
    }

    // ---- epilogue (bias already in acc) ----
    if (cnt == BM) {
#pragma unroll
        for (int mt = 0; mt < 4; mt++)
#pragma unroll
            for (int nt = 0; nt < 2; nt++)
                wmma::store_matrix_sync(
                    out + (size_t)(row0 + warp_m * 64 + mt * 16) * OUT_F
                        + ncol0 + warp_n * 32 + nt * 16,
                    acc[mt][nt], OUT_F, wmma::mem_row_major);
    } else {
        __syncthreads();   // all mma done before overwriting SMEM front
        int c4 = tid & 31, rb = tid >> 5;
#pragma unroll
        for (int half = 0; half < 2; half++) {
            if (warp_m == half) {
#pragma unroll
                for (int mt = 0; mt < 4; mt++)
#pragma unroll
                    for (int nt = 0; nt < 2; nt++)
                        wmma::store_matrix_sync(
                            smf + (mt * 16) * LDE + warp_n * 32 + nt * 16,
                            acc[mt][nt], LDE, wmma::mem_row_major);
            }
            __syncthreads();
#pragma unroll
            for (int i = 0; i < 8; i++) {
                int rl = rb + i * 8;
                int r = half * 64 + rl;
                if (r < cnt)
                    *reinterpret_cast<float4*>(out + (size_t)(row0 + r) * OUT_F + ncol0 + c4 * 4) =
                        *reinterpret_cast<const float4*>(smf + rl * LDE + c4 * 4);
            }
            __syncthreads();
        }
    }
}

// ---------------- launcher ----------------
extern "C" void kernel_launch(void* const* d_in, const int* in_sizes, int n_in,
                              void* d_out, int out_size) {
    const float* x      = (const float*)d_in[0];
    const float* weight = (const float*)d_in[1];
    const float* bias   = (const float*)d_in[2];
    const int*   net_id = (const int*)d_in[3];
    // d_in[4] = slot_id (unused: points sorted, slots contiguous within segments)
    float* out = (float*)d_out;

    cudaFuncSetAttribute(grouped_gemm_kernel,
                         cudaFuncAttributeMaxDynamicSharedMemorySize, SMEM_TOTAL);

    seg_kernel<<<NPOINTS / 256, 256>>>(net_id);
    cvt_w_kernel<<<(int)((size_t)NNET * IN_F * OUT_F / 8 / 256), 256>>>(weight);
    grouped_gemm_kernel<<<NNET * SUBTILES * NCOLS, THREADS, SMEM_TOTAL>>>(x, bias, out);
}